// round 2
// baseline (speedup 1.0000x reference)
#include <cuda_runtime.h>
#include <cuda_fp16.h>

#define N_NODES 100000
#define N_EDGES 1600000
#define D_FEAT  64
#define HALF2_PER_ROW (D_FEAT / 2)          // 32
#define SCAN_BLK 1024
#define SCAN_NBLK ((N_NODES + SCAN_BLK - 1) / SCAN_BLK)   // 98

// -------- scratch (static __device__ arrays; no allocation) --------
__device__ int g_deg[N_NODES];
__device__ int g_offsets[N_NODES + 1];
__device__ int g_cursor[N_NODES];
__device__ int g_csr_src[N_EDGES];
__device__ unsigned int g_state[SCAN_NBLK];           // decoupled-lookback state
__device__ __half2 g_h16[N_NODES * HALF2_PER_ROW];    // fp16 copy of h

// -------- kernels --------

// Fused: edge-degree count (first E threads) + fp32->fp16 convert (next N*32).
__global__ void k_prep(const float* __restrict__ h,
                       const int* __restrict__ edge_index, int E, int M) {
    int t = blockIdx.x * blockDim.x + threadIdx.x;
    if (t < E) {
        atomicAdd(&g_deg[__ldg(&edge_index[E + t])], 1);
    } else {
        int j = t - E;
        if (j < M) {
            float2 f = reinterpret_cast<const float2*>(h)[j];
            g_h16[j] = __float22half2_rn(f);
        }
    }
}

// Single-pass exclusive scan (decoupled lookback). Writes g_offsets[0..n]
// and g_cursor[0..n-1] (= offsets). State word: flag in bits[31:30]
// (1 = block aggregate, 2 = inclusive prefix), value in bits[29:0].
__global__ void k_scan(int n) {
    __shared__ int sh[SCAN_BLK];
    __shared__ int s_prefix;
    int tid = threadIdx.x;
    int bid = blockIdx.x;
    int i = bid * SCAN_BLK + tid;
    int v = (i < n) ? g_deg[i] : 0;
    sh[tid] = v;
    __syncthreads();
    #pragma unroll
    for (int off = 1; off < SCAN_BLK; off <<= 1) {
        int t = (tid >= off) ? sh[tid - off] : 0;
        __syncthreads();
        sh[tid] += t;
        __syncthreads();
    }
    int incl = sh[tid];
    int total = sh[SCAN_BLK - 1];

    if (tid == 0) {
        if (bid == 0) {
            atomicExch(&g_state[0], (2u << 30) | (unsigned)total);
            s_prefix = 0;
        } else {
            // publish aggregate immediately so successors can chain
            atomicExch(&g_state[bid], (1u << 30) | (unsigned)total);
            int prefix = 0;
            int j = bid - 1;
            while (true) {
                unsigned int s = atomicAdd(&g_state[j], 0u);
                unsigned int f = s >> 30;
                if (f == 0) continue;               // not published yet
                prefix += (int)(s & 0x3FFFFFFFu);
                if (f == 2) break;                  // inclusive prefix found
                j--;
            }
            // upgrade to inclusive prefix ASAP to unblock later blocks
            atomicExch(&g_state[bid], (2u << 30) | (unsigned)(prefix + total));
            s_prefix = prefix;
        }
    }
    __syncthreads();
    int prefix = s_prefix;

    if (i < n) {
        int excl = prefix + incl - v;
        g_offsets[i] = excl;
        g_cursor[i]  = excl;
        if (i == n - 1) g_offsets[n] = prefix + incl;
    }
}

__global__ void k_fill(const int* __restrict__ edge_index, int E) {
    int e = blockIdx.x * blockDim.x + threadIdx.x;
    if (e < E) {
        int s = __ldg(&edge_index[e]);
        int d = __ldg(&edge_index[E + e]);
        int pos = atomicAdd(&g_cursor[d], 1);
        g_csr_src[pos] = s;
    }
}

// One warp per node: max-reduce incoming src rows from the fp16 mailbox.
// Row = 64 halves = 128B; lane holds one __half2 (cols 2*lane, 2*lane+1).
__global__ void k_aggregate(float* __restrict__ out, int n) {
    int warp = (blockIdx.x * blockDim.x + threadIdx.x) >> 5;
    int lane = threadIdx.x & 31;
    if (warp >= n) return;

    int start = g_offsets[warp];
    int end   = g_offsets[warp + 1];

    const __half NEG_INF = __ushort_as_half((unsigned short)0xFC00);
    __half2 acc = __halves2half2(NEG_INF, NEG_INF);

    for (int base = start; base < end; base += 32) {
        int cnt = end - base;
        if (cnt > 32) cnt = 32;
        int myidx = (lane < cnt) ? g_csr_src[base + lane] : 0;
        #pragma unroll 4
        for (int j = 0; j < cnt; j++) {
            int s = __shfl_sync(0xffffffffu, myidx, j);
            __half2 v = g_h16[s * HALF2_PER_ROW + lane];
            acc = __hmax2(acc, v);
        }
    }

    float2 r = __half22float2(acc);
    if (end == start) { r.x = 0.0f; r.y = 0.0f; }   // isolated node -> 0
    reinterpret_cast<float2*>(out)[warp * 32 + lane] = r;
}

// -------- launch --------
extern "C" void kernel_launch(void* const* d_in, const int* in_sizes, int n_in,
                              void* d_out, int out_size) {
    const float* h = (const float*)d_in[0];
    const int* edge_index = (const int*)d_in[1];
    float* out = (float*)d_out;

    const int N = in_sizes[0] / D_FEAT;      // 100000
    const int E = in_sizes[1] / 2;           // 1600000
    const int M = N * HALF2_PER_ROW;         // 3.2M half2 elements

    void* p_deg = nullptr;
    void* p_state = nullptr;
    cudaGetSymbolAddress(&p_deg, g_deg);
    cudaGetSymbolAddress(&p_state, g_state);
    cudaMemsetAsync(p_deg, 0, (size_t)N * sizeof(int));
    cudaMemsetAsync(p_state, 0, SCAN_NBLK * sizeof(unsigned int));

    const int T = 256;

    // 1) degree count + fp16 convert (fused)
    int prep_items = E + M;
    k_prep<<<(prep_items + T - 1) / T, T>>>(h, edge_index, E, M);

    // 2) single-pass exclusive scan -> offsets + cursor
    k_scan<<<SCAN_NBLK, SCAN_BLK>>>(N);

    // 3) scatter srcs into CSR
    k_fill<<<(E + T - 1) / T, T>>>(edge_index, E);

    // 4) per-node gather-max (1 warp / node)
    int blocks = (N * 32 + T - 1) / T;
    k_aggregate<<<blocks, T>>>(out, N);
}

// round 3
// speedup vs baseline: 1.1350x; 1.1350x over previous
#include <cuda_runtime.h>

#define N_NODES 100000
#define N_EDGES 1600000
#define D_FEAT  64
#define F4_PER_ROW (D_FEAT / 4)             // 16
#define SCAN_BLK 1024
#define SCAN_NBLK ((N_NODES + SCAN_BLK - 1) / SCAN_BLK)   // 98

// -------- scratch (static __device__ arrays; no allocation) --------
__device__ int g_deg[N_NODES];
__device__ int g_offsets[N_NODES + 1];
__device__ int g_cursor[N_NODES];
__device__ int g_csr_src[N_EDGES];
__device__ unsigned int g_state[SCAN_NBLK];   // decoupled-lookback state

// -------- kernels --------

__global__ void k_count(const int* __restrict__ edge_index, int E) {
    int e = blockIdx.x * blockDim.x + threadIdx.x;
    if (e < E) atomicAdd(&g_deg[__ldg(&edge_index[E + e])], 1);
}

// Single-pass exclusive scan (decoupled lookback). Writes g_offsets[0..n]
// and g_cursor[0..n-1]. State word: flag in bits[31:30]
// (1 = aggregate, 2 = inclusive prefix), value in bits[29:0].
__global__ void k_scan(int n) {
    __shared__ int sh[SCAN_BLK];
    __shared__ int s_prefix;
    int tid = threadIdx.x;
    int bid = blockIdx.x;
    int i = bid * SCAN_BLK + tid;
    int v = (i < n) ? g_deg[i] : 0;
    sh[tid] = v;
    __syncthreads();
    #pragma unroll
    for (int off = 1; off < SCAN_BLK; off <<= 1) {
        int t = (tid >= off) ? sh[tid - off] : 0;
        __syncthreads();
        sh[tid] += t;
        __syncthreads();
    }
    int incl = sh[tid];
    int total = sh[SCAN_BLK - 1];

    if (tid == 0) {
        if (bid == 0) {
            atomicExch(&g_state[0], (2u << 30) | (unsigned)total);
            s_prefix = 0;
        } else {
            atomicExch(&g_state[bid], (1u << 30) | (unsigned)total);
            int prefix = 0;
            int j = bid - 1;
            while (true) {
                unsigned int s = atomicAdd(&g_state[j], 0u);
                unsigned int f = s >> 30;
                if (f == 0) continue;
                prefix += (int)(s & 0x3FFFFFFFu);
                if (f == 2) break;
                j--;
            }
            atomicExch(&g_state[bid], (2u << 30) | (unsigned)(prefix + total));
            s_prefix = prefix;
        }
    }
    __syncthreads();
    int prefix = s_prefix;

    if (i < n) {
        int excl = prefix + incl - v;
        g_offsets[i] = excl;
        g_cursor[i]  = excl;
        if (i == n - 1) g_offsets[n] = prefix + incl;
    }
}

__global__ void k_fill(const int* __restrict__ edge_index, int E) {
    int e = blockIdx.x * blockDim.x + threadIdx.x;
    if (e < E) {
        int s = __ldg(&edge_index[e]);
        int d = __ldg(&edge_index[E + e]);
        int pos = atomicAdd(&g_cursor[d], 1);
        g_csr_src[pos] = s;
    }
}

__device__ __forceinline__ float4 fmax4(float4 a, float4 b) {
    a.x = fmaxf(a.x, b.x); a.y = fmaxf(a.y, b.y);
    a.z = fmaxf(a.z, b.z); a.w = fmaxf(a.w, b.w);
    return a;
}

// One warp per node. Row = 64 f32 = 16 lanes x float4; half-warp hw handles
// row base+hw, so each warp iteration covers 4 rows with 4 independent
// LDG.128s. Out-of-range row indices clamp to end-1 (duplicate max = no-op),
// eliminating tail predication. Final combine: shfl.xor(16).
__global__ void k_aggregate(const float* __restrict__ h,
                            float* __restrict__ out, int n) {
    int warp = (blockIdx.x * blockDim.x + threadIdx.x) >> 5;
    int lane = threadIdx.x & 31;
    if (warp >= n) return;

    int start = g_offsets[warp];
    int end   = g_offsets[warp + 1];
    int hw = lane >> 4;        // 0 or 1: which of the pair of rows
    int fl = lane & 15;        // float4 chunk within the row

    const float NEG_INF = __int_as_float(0xff800000);
    float4 acc = make_float4(NEG_INF, NEG_INF, NEG_INF, NEG_INF);

    const float4* __restrict__ h4 = reinterpret_cast<const float4*>(h);

    for (int base = start; base < end; base += 8) {
        int e1 = end - 1;
        int i0 = min(base +     hw, e1);
        int i1 = min(base + 2 + hw, e1);
        int i2 = min(base + 4 + hw, e1);
        int i3 = min(base + 6 + hw, e1);
        int s0 = __ldg(&g_csr_src[i0]);
        int s1 = __ldg(&g_csr_src[i1]);
        int s2 = __ldg(&g_csr_src[i2]);
        int s3 = __ldg(&g_csr_src[i3]);
        float4 v0 = __ldg(&h4[s0 * F4_PER_ROW + fl]);
        float4 v1 = __ldg(&h4[s1 * F4_PER_ROW + fl]);
        float4 v2 = __ldg(&h4[s2 * F4_PER_ROW + fl]);
        float4 v3 = __ldg(&h4[s3 * F4_PER_ROW + fl]);
        acc = fmax4(acc, fmax4(fmax4(v0, v1), fmax4(v2, v3)));
    }

    // combine the two half-warps (feature chunks are aligned across hw)
    acc.x = fmaxf(acc.x, __shfl_xor_sync(0xffffffffu, acc.x, 16));
    acc.y = fmaxf(acc.y, __shfl_xor_sync(0xffffffffu, acc.y, 16));
    acc.z = fmaxf(acc.z, __shfl_xor_sync(0xffffffffu, acc.z, 16));
    acc.w = fmaxf(acc.w, __shfl_xor_sync(0xffffffffu, acc.w, 16));

    if (end == start) acc = make_float4(0.f, 0.f, 0.f, 0.f);

    if (lane < 16)
        reinterpret_cast<float4*>(out)[warp * F4_PER_ROW + fl] = acc;
}

// -------- launch --------
extern "C" void kernel_launch(void* const* d_in, const int* in_sizes, int n_in,
                              void* d_out, int out_size) {
    const float* h = (const float*)d_in[0];
    const int* edge_index = (const int*)d_in[1];
    float* out = (float*)d_out;

    const int N = in_sizes[0] / D_FEAT;      // 100000
    const int E = in_sizes[1] / 2;           // 1600000

    void* p_deg = nullptr;
    void* p_state = nullptr;
    cudaGetSymbolAddress(&p_deg, g_deg);
    cudaGetSymbolAddress(&p_state, g_state);
    cudaMemsetAsync(p_deg, 0, (size_t)N * sizeof(int));
    cudaMemsetAsync(p_state, 0, SCAN_NBLK * sizeof(unsigned int));

    const int T = 256;

    k_count<<<(E + T - 1) / T, T>>>(edge_index, E);
    k_scan<<<SCAN_NBLK, SCAN_BLK>>>(N);
    k_fill<<<(E + T - 1) / T, T>>>(edge_index, E);

    int blocks = (N * 32 + T - 1) / T;
    k_aggregate<<<blocks, T>>>(h, out, N);
}

// round 4
// speedup vs baseline: 1.1541x; 1.0169x over previous
#include <cuda_runtime.h>

#define N_NODES   100000
#define N_EDGES   1600000
#define D_FEAT    64
#define F4_PER_ROW (D_FEAT / 4)       // 16
#define G_BLOCKS  512
#define T_THREADS 256
#define CHUNK     196                 // ceil(100000 / 512)

// -------- scratch (static __device__; zero-initialized at load) --------
__device__ int g_deg[N_NODES];              // re-zeroed by k_aggregate each run
__device__ int g_offsets[N_NODES + 1];
__device__ int g_cursor[N_NODES];
__device__ int g_csr_src[N_EDGES];
__device__ int g_bsum[G_BLOCKS];
__device__ int g_bprefix[G_BLOCKS];
__device__ unsigned int g_bar;              // reset by k_aggregate each run

// Grid-wide barrier: monotonic counter, target = phase * G_BLOCKS.
__device__ __forceinline__ void grid_barrier(unsigned int target) {
    __syncthreads();
    if (threadIdx.x == 0) {
        __threadfence();
        atomicAdd(&g_bar, 1u);
        while (atomicAdd(&g_bar, 0u) < target) { }
    }
    __syncthreads();
}

// One persistent kernel: degree count -> exclusive scan -> CSR fill.
// All cross-phase traffic goes through L2 (__ldcg/__stcg/atomics).
__global__ void __launch_bounds__(T_THREADS, 4)
k_build(const int* __restrict__ edge_index, int E, int N) {
    __shared__ int sh[T_THREADS];       // chunk inclusive scan (persists across barriers)
    __shared__ int sh_top[T_THREADS];   // block-0 top-level scan
    const int tid  = threadIdx.x;
    const int bid  = blockIdx.x;
    const int gtid = bid * T_THREADS + tid;
    const int NT   = G_BLOCKS * T_THREADS;

    // ---- Phase 1: degree count ----
    for (int i = gtid; i < E; i += NT)
        atomicAdd(&g_deg[__ldg(&edge_index[E + i])], 1);
    grid_barrier(1u * G_BLOCKS);

    // ---- Phase 2a: per-block inclusive scan of its CHUNK of degrees ----
    const int base = bid * CHUNK;
    int v = 0;
    if (tid < CHUNK && base + tid < N) v = __ldcg(&g_deg[base + tid]);
    sh[tid] = v;
    __syncthreads();
    #pragma unroll
    for (int off = 1; off < T_THREADS; off <<= 1) {
        int t = (tid >= off) ? sh[tid - off] : 0;
        __syncthreads();
        sh[tid] += t;
        __syncthreads();
    }
    if (tid == T_THREADS - 1) __stcg(&g_bsum[bid], sh[tid]);
    grid_barrier(2u * G_BLOCKS);

    // ---- Phase 2b: block 0 exclusive-scans the 512 block sums ----
    if (bid == 0) {
        int a0 = __ldcg(&g_bsum[2 * tid]);
        int a1 = __ldcg(&g_bsum[2 * tid + 1]);
        int s = a0 + a1;
        sh_top[tid] = s;
        __syncthreads();
        #pragma unroll
        for (int off = 1; off < T_THREADS; off <<= 1) {
            int t = (tid >= off) ? sh_top[tid - off] : 0;
            __syncthreads();
            sh_top[tid] += t;
            __syncthreads();
        }
        int excl = sh_top[tid] - s;
        __stcg(&g_bprefix[2 * tid],     excl);
        __stcg(&g_bprefix[2 * tid + 1], excl + a0);
        if (tid == T_THREADS - 1) __stcg(&g_offsets[N], sh_top[tid]);
    }
    grid_barrier(3u * G_BLOCKS);

    // ---- Phase 2c: write offsets + cursor (exclusive = prefix + incl - v) ----
    {
        int p = __ldcg(&g_bprefix[bid]);
        if (tid < CHUNK && base + tid < N) {
            int excl = p + sh[tid] - v;
            __stcg(&g_offsets[base + tid], excl);
            __stcg(&g_cursor[base + tid],  excl);
        }
    }
    grid_barrier(4u * G_BLOCKS);

    // ---- Phase 3: scatter srcs into CSR ----
    for (int i = gtid; i < E; i += NT) {
        int s = __ldg(&edge_index[i]);
        int d = __ldg(&edge_index[E + i]);
        int pos = atomicAdd(&g_cursor[d], 1);
        __stcg(&g_csr_src[pos], s);
    }
}

__device__ __forceinline__ float4 fmax4(float4 a, float4 b) {
    a.x = fmaxf(a.x, b.x); a.y = fmaxf(a.y, b.y);
    a.z = fmaxf(a.z, b.z); a.w = fmaxf(a.w, b.w);
    return a;
}

// One warp per node; half-warp per row; 4 rows per iteration via 4 LDG.128.
// Out-of-range indices clamp to end-1 (duplicate under max = no-op).
// Also performs next-replay housekeeping (reset barrier ctr + re-zero deg).
__global__ void k_aggregate(const float* __restrict__ h,
                            float* __restrict__ out, int n) {
    int gtid = blockIdx.x * blockDim.x + threadIdx.x;
    if (gtid == 0) g_bar = 0;                 // reset for next replay
    if (gtid < n) __stcg(&g_deg[gtid], 0);    // re-zero degrees for next replay

    int warp = gtid >> 5;
    int lane = threadIdx.x & 31;
    if (warp >= n) return;

    int start = g_offsets[warp];
    int end   = g_offsets[warp + 1];
    int hw = lane >> 4;
    int fl = lane & 15;

    const float NEG_INF = __int_as_float(0xff800000);
    float4 acc = make_float4(NEG_INF, NEG_INF, NEG_INF, NEG_INF);

    const float4* __restrict__ h4 = reinterpret_cast<const float4*>(h);

    for (int base = start; base < end; base += 8) {
        int e1 = end - 1;
        int i0 = min(base +     hw, e1);
        int i1 = min(base + 2 + hw, e1);
        int i2 = min(base + 4 + hw, e1);
        int i3 = min(base + 6 + hw, e1);
        int s0 = __ldg(&g_csr_src[i0]);
        int s1 = __ldg(&g_csr_src[i1]);
        int s2 = __ldg(&g_csr_src[i2]);
        int s3 = __ldg(&g_csr_src[i3]);
        float4 v0 = __ldg(&h4[s0 * F4_PER_ROW + fl]);
        float4 v1 = __ldg(&h4[s1 * F4_PER_ROW + fl]);
        float4 v2 = __ldg(&h4[s2 * F4_PER_ROW + fl]);
        float4 v3 = __ldg(&h4[s3 * F4_PER_ROW + fl]);
        acc = fmax4(acc, fmax4(fmax4(v0, v1), fmax4(v2, v3)));
    }

    acc.x = fmaxf(acc.x, __shfl_xor_sync(0xffffffffu, acc.x, 16));
    acc.y = fmaxf(acc.y, __shfl_xor_sync(0xffffffffu, acc.y, 16));
    acc.z = fmaxf(acc.z, __shfl_xor_sync(0xffffffffu, acc.z, 16));
    acc.w = fmaxf(acc.w, __shfl_xor_sync(0xffffffffu, acc.w, 16));

    if (end == start) acc = make_float4(0.f, 0.f, 0.f, 0.f);

    if (lane < 16)
        reinterpret_cast<float4*>(out)[warp * F4_PER_ROW + fl] = acc;
}

// -------- launch: exactly two graph nodes --------
extern "C" void kernel_launch(void* const* d_in, const int* in_sizes, int n_in,
                              void* d_out, int out_size) {
    const float* h = (const float*)d_in[0];
    const int* edge_index = (const int*)d_in[1];
    float* out = (float*)d_out;

    const int N = in_sizes[0] / D_FEAT;      // 100000
    const int E = in_sizes[1] / 2;           // 1600000

    k_build<<<G_BLOCKS, T_THREADS>>>(edge_index, E, N);

    int blocks = (N * 32 + T_THREADS - 1) / T_THREADS;   // 12500
    k_aggregate<<<blocks, T_THREADS>>>(h, out, N);
}